// round 3
// baseline (speedup 1.0000x reference)
#include <cuda_runtime.h>
#include <cuda_bf16.h>
#include <cstdint>

// ---------------------------------------------------------------------------
// RnnTfModel: emb lookup -> LSTM1 (seq) -> LSTM2 (last) -> heads
// B=512, T=1024, D=H=64, 4H=256, V=8193
//
// R3: U1+W2 register-resident (128 regs/thread), U2 in shared (no spill),
//     h broadcast from smem, 3 barriers/step, packed f32x2 FMA.
// ---------------------------------------------------------------------------

#define B_   512
#define T_   1024
#define D_   64
#define G4_  256
#define V_   8193
#define NB_  4
#define NBLK_ 128
#define THR_ 256

using ull = unsigned long long;

__device__ float g_table[V_ * G4_];   // projected embedding table (8.4 MB)
__device__ float g_h2[B_ * D_];       // final layer-2 hidden state

__device__ __forceinline__ void ffma2(ull& d, ull a, ull b) {
    asm("fma.rn.f32x2 %0, %1, %2, %0;" : "+l"(d) : "l"(a), "l"(b));
}
__device__ __forceinline__ float2 unpack2(ull v) {
    float2 f;
    asm("mov.b64 {%0, %1}, %2;" : "=f"(f.x), "=f"(f.y) : "l"(v));
    return f;
}
__device__ __forceinline__ ull pack2(float lo, float hi) {
    ull v;
    asm("mov.b64 %0, {%1, %2};" : "=l"(v) : "f"(lo), "f"(hi));
    return v;
}
__device__ __forceinline__ float sigm_(float x) {
    return 1.0f / (1.0f + __expf(-x));
}
__device__ __forceinline__ float tanh_(float x) {
    float e = __expf(-2.0f * x);
    return (1.0f - e) / (1.0f + e);
}

// ---------------------------------------------------------------------------
// Kernel 1: projected embedding table  (g_table = emb @ W1 + b1)
// ---------------------------------------------------------------------------
__global__ void k_embproj(const float* __restrict__ emb,
                          const float* __restrict__ W1,
                          const float* __restrict__ b1) {
    int v = blockIdx.x;
    int j = threadIdx.x;  // 256 threads, one output each
    __shared__ float e[D_];
    if (j < D_) e[j] = emb[v * D_ + j];
    __syncthreads();
    float acc = b1[j];
#pragma unroll
    for (int k = 0; k < D_; k++) acc += e[k] * __ldg(&W1[k * G4_ + j]);
    g_table[v * G4_ + j] = acc;
}

// ---------------------------------------------------------------------------
// Kernel 2: fused persistent 2-layer LSTM.
// Thread j in [0,256) owns output column j of both layers' gate matvecs.
// U1 and W2 columns live in registers (64+64 regs of f32x2 pairs).
// U2 lives in shared memory (k-interleaved float4).
// Dynamic smem layout (floats):
//   [0,     16384)  U2q    : (k4*256+j)*4+kk = U2[4k4+kk][j], k4 in [0,16)
//   [16384, 16896)  hc     : 4 rows x 128 : [0,64)=h1, [64,128)=h2
//   [16896, 17920)  zbuf1  : 4 rows x 256
//   [17920, 18944)  zbuf2  : 4 rows x 256
//   [18944, 23040)  code_s : 4 rows x 1024 int32
// total 92160 bytes
// ---------------------------------------------------------------------------
#define SM_U2    0
#define SM_HC    16384
#define SM_Z1    16896
#define SM_Z2    17920
#define SM_CODE  18944
#define SMEM_BYTES (23040 * 4)

__global__ void __launch_bounds__(THR_, 1)
k_lstm(const int* __restrict__ code_in,
       const float* __restrict__ U1,
       const float* __restrict__ W2,
       const float* __restrict__ U2,
       const float* __restrict__ b2) {
    extern __shared__ __align__(16) float smem[];
    float* U2q    = smem + SM_U2;
    float* hc     = smem + SM_HC;
    float* zbuf1  = smem + SM_Z1;
    float* zbuf2  = smem + SM_Z2;
    int*   code_s = (int*)(smem + SM_CODE);

    const int j  = threadIdx.x;
    const int r_ = j >> 6;      // row for c/h update role
    const int u_ = j & 63;      // hidden unit for c/h update role
    const int b0 = blockIdx.x * NB_;

    // ---- U1, W2 columns into registers (packed over adjacent k) ----
    ull w1r[32];                 // U1[2k2][j], U1[2k2+1][j]
#pragma unroll
    for (int k2 = 0; k2 < 32; k2++)
        w1r[k2] = pack2(__ldg(&U1[(2 * k2) * G4_ + j]),
                        __ldg(&U1[(2 * k2 + 1) * G4_ + j]));
    ull w2r[32];                 // W2[2k2][j], W2[2k2+1][j]
#pragma unroll
    for (int k2 = 0; k2 < 32; k2++)
        w2r[k2] = pack2(__ldg(&W2[(2 * k2) * G4_ + j]),
                        __ldg(&W2[(2 * k2 + 1) * G4_ + j]));

    // ---- U2 into shared, k-interleaved-by-4 ----
    for (int i = j; i < D_ * G4_; i += THR_) {
        int k = i >> 8, jj = i & 255;
        int k4 = k >> 2, kk = k & 3;
        U2q[(k4 * G4_ + jj) * 4 + kk] = U2[i];
    }
    // ---- codes for this block's 4 rows ----
    for (int i = j; i < NB_ * T_; i += THR_) {
        int r = i >> 10, t = i & (T_ - 1);
        code_s[i] = code_in[(b0 + r) * T_ + t];
    }
    // ---- zero h state ----
    hc[j] = 0.0f;
    hc[j + 256] = 0.0f;
    __syncthreads();

    const float b2j = b2[j];
    float c1 = 0.0f, c2 = 0.0f;

    // prefetch xz for t=0
    float cur[NB_];
#pragma unroll
    for (int r = 0; r < NB_; r++)
        cur[r] = __ldg(&g_table[(size_t)code_s[r * T_] * G4_ + j]);

    const bool isg = ((j >> 6) == 2);  // gate index 2 = g (tanh)

    for (int t = 0; t < T_; t++) {
        // prefetch next timestep's input projection
        float nxt[NB_];
        int tn = (t + 1 < T_) ? (t + 1) : (T_ - 1);
#pragma unroll
        for (int r = 0; r < NB_; r++)
            nxt[r] = __ldg(&g_table[(size_t)code_s[r * T_ + tn] * G4_ + j]);

        // ---------------- layer 1 matvec: z1 = xz + h1 @ U1 ----------------
        ull a0 = 0, a1 = 0, a2 = 0, a3 = 0;
#pragma unroll
        for (int k4 = 0; k4 < 16; k4++) {
            ulonglong2 h0 = *(const ulonglong2*)&hc[0 * 128 + 4 * k4];
            ulonglong2 h1 = *(const ulonglong2*)&hc[1 * 128 + 4 * k4];
            ulonglong2 h2 = *(const ulonglong2*)&hc[2 * 128 + 4 * k4];
            ulonglong2 h3 = *(const ulonglong2*)&hc[3 * 128 + 4 * k4];
            ffma2(a0, h0.x, w1r[2 * k4]);     ffma2(a1, h1.x, w1r[2 * k4]);
            ffma2(a2, h2.x, w1r[2 * k4]);     ffma2(a3, h3.x, w1r[2 * k4]);
            ffma2(a0, h0.y, w1r[2 * k4 + 1]); ffma2(a1, h1.y, w1r[2 * k4 + 1]);
            ffma2(a2, h2.y, w1r[2 * k4 + 1]); ffma2(a3, h3.y, w1r[2 * k4 + 1]);
        }
        {
            ull aa[NB_] = {a0, a1, a2, a3};
#pragma unroll
            for (int r = 0; r < NB_; r++) {
                float2 p = unpack2(aa[r]);
                float z = cur[r] + p.x + p.y;
                zbuf1[r * G4_ + j] = isg ? tanh_(z) : sigm_(z);
            }
        }
        __syncthreads();   // sync1: zbuf1 ready
        {
            float iv = zbuf1[r_ * G4_ + u_];
            float fv = zbuf1[r_ * G4_ + 64 + u_];
            float gv = zbuf1[r_ * G4_ + 128 + u_];
            float ov = zbuf1[r_ * G4_ + 192 + u_];
            c1 = fv * c1 + iv * gv;
            hc[r_ * 128 + u_] = ov * tanh_(c1);   // h1_t
        }
        __syncthreads();   // sync2: h1_t ready

        // -------- layer 2 matvec: z2 = b2 + h1_t @ W2 + h2_{t-1} @ U2 ------
        a0 = a1 = a2 = a3 = 0;
        // W2 part (registers), k over h1
#pragma unroll
        for (int k4 = 0; k4 < 16; k4++) {
            ulonglong2 h0 = *(const ulonglong2*)&hc[0 * 128 + 4 * k4];
            ulonglong2 h1 = *(const ulonglong2*)&hc[1 * 128 + 4 * k4];
            ulonglong2 h2 = *(const ulonglong2*)&hc[2 * 128 + 4 * k4];
            ulonglong2 h3 = *(const ulonglong2*)&hc[3 * 128 + 4 * k4];
            ffma2(a0, h0.x, w2r[2 * k4]);     ffma2(a1, h1.x, w2r[2 * k4]);
            ffma2(a2, h2.x, w2r[2 * k4]);     ffma2(a3, h3.x, w2r[2 * k4]);
            ffma2(a0, h0.y, w2r[2 * k4 + 1]); ffma2(a1, h1.y, w2r[2 * k4 + 1]);
            ffma2(a2, h2.y, w2r[2 * k4 + 1]); ffma2(a3, h3.y, w2r[2 * k4 + 1]);
        }
        // U2 part (shared), k over h2
#pragma unroll
        for (int k4 = 0; k4 < 16; k4++) {
            ulonglong2 uq = *(const ulonglong2*)&U2q[(k4 * G4_ + j) * 4];
            ulonglong2 h0 = *(const ulonglong2*)&hc[0 * 128 + 64 + 4 * k4];
            ulonglong2 h1 = *(const ulonglong2*)&hc[1 * 128 + 64 + 4 * k4];
            ulonglong2 h2 = *(const ulonglong2*)&hc[2 * 128 + 64 + 4 * k4];
            ulonglong2 h3 = *(const ulonglong2*)&hc[3 * 128 + 64 + 4 * k4];
            ffma2(a0, h0.x, uq.x); ffma2(a1, h1.x, uq.x);
            ffma2(a2, h2.x, uq.x); ffma2(a3, h3.x, uq.x);
            ffma2(a0, h0.y, uq.y); ffma2(a1, h1.y, uq.y);
            ffma2(a2, h2.y, uq.y); ffma2(a3, h3.y, uq.y);
        }
        {
            ull aa[NB_] = {a0, a1, a2, a3};
#pragma unroll
            for (int r = 0; r < NB_; r++) {
                float2 p = unpack2(aa[r]);
                float z = b2j + p.x + p.y;
                zbuf2[r * G4_ + j] = isg ? tanh_(z) : sigm_(z);
            }
        }
        __syncthreads();   // sync3: zbuf2 ready
        {
            float iv = zbuf2[r_ * G4_ + u_];
            float fv = zbuf2[r_ * G4_ + 64 + u_];
            float gv = zbuf2[r_ * G4_ + 128 + u_];
            float ov = zbuf2[r_ * G4_ + 192 + u_];
            c2 = fv * c2 + iv * gv;
            hc[r_ * 128 + 64 + u_] = ov * tanh_(c2);  // h2_t
        }
        // no barrier: h2_t is next read after sync1+sync2 of step t+1;
        // WAR on zbuf2 protected by sync1 of t+1.

#pragma unroll
        for (int r = 0; r < NB_; r++) cur[r] = nxt[r];
    }

    __syncthreads();
    // final h2 -> global
    g_h2[(b0 + r_) * D_ + u_] = hc[r_ * 128 + 64 + u_];
}

// ---------------------------------------------------------------------------
// Kernel 3: heads.  out[0:1024] = softmax head, out[1024:2048] = langmodel.
// ---------------------------------------------------------------------------
__global__ void k_head(const float* __restrict__ aux,
                       const float* __restrict__ Wlm, const float* __restrict__ blm,
                       const float* __restrict__ gamma, const float* __restrict__ beta,
                       const float* __restrict__ mean, const float* __restrict__ var,
                       const float* __restrict__ W3, const float* __restrict__ b3,
                       const float* __restrict__ W4, const float* __restrict__ b4,
                       float* __restrict__ out) {
    int b = blockIdx.x;
    int t = threadIdx.x;  // 128 threads
    __shared__ float h2s[64], zbn[66], hid[32];

    if (t < 64) h2s[t] = g_h2[b * 64 + t];
    __syncthreads();
    if (t < 66) {
        float z = (t < 2) ? aux[b * 2 + t] : h2s[t - 2];
        zbn[t] = gamma[t] * (z - mean[t]) * rsqrtf(var[t] + 1e-3f) + beta[t];
    }
    __syncthreads();
    if (t < 32) {
        float acc = b3[t];
#pragma unroll
        for (int k = 0; k < 66; k++) acc += zbn[k] * __ldg(&W3[k * 32 + t]);
        hid[t] = fmaxf(acc, 0.0f);
    }
    __syncthreads();
    if (t == 0) {
        float o0 = b4[0], o1 = b4[1];
#pragma unroll
        for (int k = 0; k < 32; k++) {
            o0 += hid[k] * __ldg(&W4[k * 2 + 0]);
            o1 += hid[k] * __ldg(&W4[k * 2 + 1]);
        }
        float m = fmaxf(o0, o1);
        float e0 = __expf(o0 - m), e1 = __expf(o1 - m);
        float inv = 1.0f / (e0 + e1);
        out[b * 2 + 0] = e0 * inv;
        out[b * 2 + 1] = e1 * inv;

        float l0 = blm[0], l1 = blm[1];
#pragma unroll
        for (int k = 0; k < 64; k++) {
            l0 += h2s[k] * __ldg(&Wlm[k * 2 + 0]);
            l1 += h2s[k] * __ldg(&Wlm[k * 2 + 1]);
        }
        out[B_ * 2 + b * 2 + 0] = sigm_(l0);
        out[B_ * 2 + b * 2 + 1] = sigm_(l1);
    }
}

// ---------------------------------------------------------------------------
// launcher
// inputs: 0 aux_in, 1 code_in, 2 emb, 3 W1, 4 U1, 5 b1, 6 W2, 7 U2, 8 b2,
//         9 Wlm, 10 blm, 11 bn_gamma, 12 bn_beta, 13 bn_mean, 14 bn_var,
//         15 W3, 16 b3, 17 W4, 18 b4
// ---------------------------------------------------------------------------
extern "C" void kernel_launch(void* const* d_in, const int* in_sizes, int n_in,
                              void* d_out, int out_size) {
    const float* aux   = (const float*)d_in[0];
    const int*   code  = (const int*)d_in[1];
    const float* emb   = (const float*)d_in[2];
    const float* W1    = (const float*)d_in[3];
    const float* U1    = (const float*)d_in[4];
    const float* b1    = (const float*)d_in[5];
    const float* W2    = (const float*)d_in[6];
    const float* U2    = (const float*)d_in[7];
    const float* b2    = (const float*)d_in[8];
    const float* Wlm   = (const float*)d_in[9];
    const float* blm   = (const float*)d_in[10];
    const float* gamma = (const float*)d_in[11];
    const float* beta  = (const float*)d_in[12];
    const float* mean  = (const float*)d_in[13];
    const float* var   = (const float*)d_in[14];
    const float* W3    = (const float*)d_in[15];
    const float* b3    = (const float*)d_in[16];
    const float* W4    = (const float*)d_in[17];
    const float* b4    = (const float*)d_in[18];
    float* out = (float*)d_out;

    cudaFuncSetAttribute(k_lstm, cudaFuncAttributeMaxDynamicSharedMemorySize,
                         SMEM_BYTES);

    k_embproj<<<V_, 256>>>(emb, W1, b1);
    k_lstm<<<NBLK_, THR_, SMEM_BYTES>>>(code, U1, W2, U2, b2);
    k_head<<<B_, 128>>>(aux, Wlm, blm, gamma, beta, mean, var, W3, b3, W4, b4,
                        out);
}

// round 4
// speedup vs baseline: 1.0005x; 1.0005x over previous
#include <cuda_runtime.h>
#include <cuda_bf16.h>
#include <cstdint>

// ---------------------------------------------------------------------------
// RnnTfModel: emb lookup -> LSTM1 (seq) -> LSTM2 (last) -> heads
// B=512, T=1024, D=H=64, 4H=256, V=8193
//
// R4: U1+W2 register-resident (128 regs), U2 in shared; all matvec loops
//     explicitly software-pipelined (2-stage double-buffered loads) so LDS
//     latency hides under FMA and the LSU/FMA pipes overlap.
// ---------------------------------------------------------------------------

#define B_   512
#define T_   1024
#define D_   64
#define G4_  256
#define V_   8193
#define NB_  4
#define NBLK_ 128
#define THR_ 256

using ull = unsigned long long;

__device__ float g_table[V_ * G4_];   // projected embedding table (8.4 MB)
__device__ float g_h2[B_ * D_];       // final layer-2 hidden state

__device__ __forceinline__ void ffma2(ull& d, ull a, ull b) {
    asm("fma.rn.f32x2 %0, %1, %2, %0;" : "+l"(d) : "l"(a), "l"(b));
}
__device__ __forceinline__ float2 unpack2(ull v) {
    float2 f;
    asm("mov.b64 {%0, %1}, %2;" : "=f"(f.x), "=f"(f.y) : "l"(v));
    return f;
}
__device__ __forceinline__ ull pack2(float lo, float hi) {
    ull v;
    asm("mov.b64 %0, {%1, %2};" : "=l"(v) : "f"(lo), "f"(hi));
    return v;
}
__device__ __forceinline__ float sigm_(float x) {
    return 1.0f / (1.0f + __expf(-x));
}
__device__ __forceinline__ float tanh_(float x) {
    float e = __expf(-2.0f * x);
    return (1.0f - e) / (1.0f + e);
}

// ---------------------------------------------------------------------------
// Kernel 1: projected embedding table  (g_table = emb @ W1 + b1)
// ---------------------------------------------------------------------------
__global__ void k_embproj(const float* __restrict__ emb,
                          const float* __restrict__ W1,
                          const float* __restrict__ b1) {
    int v = blockIdx.x;
    int j = threadIdx.x;  // 256 threads, one output each
    __shared__ float e[D_];
    if (j < D_) e[j] = emb[v * D_ + j];
    __syncthreads();
    float acc = b1[j];
#pragma unroll
    for (int k = 0; k < D_; k++) acc += e[k] * __ldg(&W1[k * G4_ + j]);
    g_table[v * G4_ + j] = acc;
}

// ---------------------------------------------------------------------------
// Kernel 2: fused persistent 2-layer LSTM.
// Thread j in [0,256) owns output column j of both layers' gate matvecs.
// U1, W2 columns in registers (f32x2 pairs); U2 in shared (k-interleaved x4).
// Dynamic smem layout (floats):
//   [0,     16384)  U2q    : (k4*256+j)*4+kk = U2[4k4+kk][j]
//   [16384, 16896)  hc     : 4 rows x 128 : [0,64)=h1, [64,128)=h2
//   [16896, 17920)  zbuf1  : 4 rows x 256
//   [17920, 18944)  zbuf2  : 4 rows x 256
//   [18944, 23040)  code_s : 4 rows x 1024 int32
// ---------------------------------------------------------------------------
#define SM_U2    0
#define SM_HC    16384
#define SM_Z1    16896
#define SM_Z2    17920
#define SM_CODE  18944
#define SMEM_BYTES (23040 * 4)

// load h vectors (16B) of all 4 rows at k4 into a 4-wide ull2 buffer
#define LOADH(dst, base, k4) do {                                         \
    dst[0] = *(const ulonglong2*)&hc[0 * 128 + (base) + 4 * (k4)];        \
    dst[1] = *(const ulonglong2*)&hc[1 * 128 + (base) + 4 * (k4)];        \
    dst[2] = *(const ulonglong2*)&hc[2 * 128 + (base) + 4 * (k4)];        \
    dst[3] = *(const ulonglong2*)&hc[3 * 128 + (base) + 4 * (k4)];        \
} while (0)

// 8 packed fma on a 4-row buffer with weight pair (wlo, whi)
#define FMA4(buf, wlo, whi) do {                                          \
    ffma2(a0, buf[0].x, (wlo)); ffma2(a1, buf[1].x, (wlo));               \
    ffma2(a2, buf[2].x, (wlo)); ffma2(a3, buf[3].x, (wlo));               \
    ffma2(a0, buf[0].y, (whi)); ffma2(a1, buf[1].y, (whi));               \
    ffma2(a2, buf[2].y, (whi)); ffma2(a3, buf[3].y, (whi));               \
} while (0)

__global__ void __launch_bounds__(THR_, 1)
k_lstm(const int* __restrict__ code_in,
       const float* __restrict__ U1,
       const float* __restrict__ W2,
       const float* __restrict__ U2,
       const float* __restrict__ b2) {
    extern __shared__ __align__(16) float smem[];
    float* U2q    = smem + SM_U2;
    float* hc     = smem + SM_HC;
    float* zbuf1  = smem + SM_Z1;
    float* zbuf2  = smem + SM_Z2;
    int*   code_s = (int*)(smem + SM_CODE);

    const int j  = threadIdx.x;
    const int r_ = j >> 6;      // row for c/h update role
    const int u_ = j & 63;      // hidden unit for c/h update role
    const int b0 = blockIdx.x * NB_;

    // ---- U1, W2 columns into registers (packed over adjacent k) ----
    ull w1r[32];
#pragma unroll
    for (int k2 = 0; k2 < 32; k2++)
        w1r[k2] = pack2(__ldg(&U1[(2 * k2) * G4_ + j]),
                        __ldg(&U1[(2 * k2 + 1) * G4_ + j]));
    ull w2r[32];
#pragma unroll
    for (int k2 = 0; k2 < 32; k2++)
        w2r[k2] = pack2(__ldg(&W2[(2 * k2) * G4_ + j]),
                        __ldg(&W2[(2 * k2 + 1) * G4_ + j]));

    // ---- U2 into shared, k-interleaved-by-4 ----
    for (int i = j; i < D_ * G4_; i += THR_) {
        int k = i >> 8, jj = i & 255;
        int k4 = k >> 2, kk = k & 3;
        U2q[(k4 * G4_ + jj) * 4 + kk] = U2[i];
    }
    // ---- codes for this block's 4 rows ----
    for (int i = j; i < NB_ * T_; i += THR_) {
        int r = i >> 10, t = i & (T_ - 1);
        code_s[i] = code_in[(b0 + r) * T_ + t];
    }
    // ---- zero h state ----
    hc[j] = 0.0f;
    hc[j + 256] = 0.0f;
    __syncthreads();

    const float b2j = b2[j];
    float c1 = 0.0f, c2 = 0.0f;

    // prefetch xz for t=0
    float cur[NB_];
#pragma unroll
    for (int r = 0; r < NB_; r++)
        cur[r] = __ldg(&g_table[(size_t)code_s[r * T_] * G4_ + j]);

    const bool isg = ((j >> 6) == 2);  // gate index 2 = g (tanh)

    for (int t = 0; t < T_; t++) {
        // prefetch next timestep's input projection (L2-latency hidden by step)
        float nxt[NB_];
        int tn = (t + 1 < T_) ? (t + 1) : (T_ - 1);
#pragma unroll
        for (int r = 0; r < NB_; r++)
            nxt[r] = __ldg(&g_table[(size_t)code_s[r * T_ + tn] * G4_ + j]);

        ull a0, a1, a2, a3;
        ulonglong2 pa[4], pb[4];

        // ============ phase A: z1 = xz + U1 . h1_{t-1}  (k=0..63) ==========
        a0 = a1 = a2 = a3 = 0;
        LOADH(pa, 0, 0);
#pragma unroll
        for (int k4 = 0; k4 < 16; k4 += 2) {
            LOADH(pb, 0, k4 + 1);                 // prefetch odd iter
            FMA4(pa, w1r[2 * k4], w1r[2 * k4 + 1]);
            if (k4 + 2 < 16) LOADH(pa, 0, k4 + 2); // prefetch next even iter
            FMA4(pb, w1r[2 * k4 + 2], w1r[2 * k4 + 3]);
        }
        {
#pragma unroll
            for (int r = 0; r < NB_; r++) {
                ull aa = (r == 0) ? a0 : (r == 1) ? a1 : (r == 2) ? a2 : a3;
                float2 p = unpack2(aa);
                float z = cur[r] + p.x + p.y;
                zbuf1[r * G4_ + j] = isg ? tanh_(z) : sigm_(z);
            }
        }
        __syncthreads();   // S1: zbuf1 ready
        {
            float iv = zbuf1[r_ * G4_ + u_];
            float fv = zbuf1[r_ * G4_ + 64 + u_];
            float gv = zbuf1[r_ * G4_ + 128 + u_];
            float ov = zbuf1[r_ * G4_ + 192 + u_];
            c1 = fv * c1 + iv * gv;
            hc[r_ * 128 + u_] = ov * tanh_(c1);   // h1_t
        }
        __syncthreads();   // S2: h1_t ready

        // ===== phase B1: acc = U2 . h2_{t-1}  (U2 from smem, pipelined) ====
        a0 = a1 = a2 = a3 = 0;
        {
            ulonglong2 qa, qb;
            LOADH(pa, 64, 0);
            qa = *(const ulonglong2*)&U2q[(0 * G4_ + j) * 4];
#pragma unroll
            for (int k4 = 0; k4 < 16; k4 += 2) {
                LOADH(pb, 64, k4 + 1);
                qb = *(const ulonglong2*)&U2q[((k4 + 1) * G4_ + j) * 4];
                FMA4(pa, qa.x, qa.y);
                if (k4 + 2 < 16) {
                    LOADH(pa, 64, k4 + 2);
                    qa = *(const ulonglong2*)&U2q[((k4 + 2) * G4_ + j) * 4];
                }
                FMA4(pb, qb.x, qb.y);
            }
        }

        // ===== phase B2: acc += W2 . h1_t  (W2 regs, pipelined h1 loads) ===
        LOADH(pa, 0, 0);
#pragma unroll
        for (int k4 = 0; k4 < 16; k4 += 2) {
            LOADH(pb, 0, k4 + 1);
            FMA4(pa, w2r[2 * k4], w2r[2 * k4 + 1]);
            if (k4 + 2 < 16) LOADH(pa, 0, k4 + 2);
            FMA4(pb, w2r[2 * k4 + 2], w2r[2 * k4 + 3]);
        }
        {
#pragma unroll
            for (int r = 0; r < NB_; r++) {
                ull aa = (r == 0) ? a0 : (r == 1) ? a1 : (r == 2) ? a2 : a3;
                float2 p = unpack2(aa);
                float z = b2j + p.x + p.y;
                zbuf2[r * G4_ + j] = isg ? tanh_(z) : sigm_(z);
            }
        }
        __syncthreads();   // S3: zbuf2 ready
        {
            float iv = zbuf2[r_ * G4_ + u_];
            float fv = zbuf2[r_ * G4_ + 64 + u_];
            float gv = zbuf2[r_ * G4_ + 128 + u_];
            float ov = zbuf2[r_ * G4_ + 192 + u_];
            c2 = fv * c2 + iv * gv;
            hc[r_ * 128 + 64 + u_] = ov * tanh_(c2);  // h2_t
        }
        // no barrier: h2_t next read in B1 of t+1, after S1+S2 of t+1.
        // zbuf2 WAR protected by S1 of t+1; zbuf1 WAR protected by S2,S3.

#pragma unroll
        for (int r = 0; r < NB_; r++) cur[r] = nxt[r];
    }

    __syncthreads();
    // final h2 -> global
    g_h2[(b0 + r_) * D_ + u_] = hc[r_ * 128 + 64 + u_];
}

// ---------------------------------------------------------------------------
// Kernel 3: heads.  out[0:1024] = softmax head, out[1024:2048] = langmodel.
// ---------------------------------------------------------------------------
__global__ void k_head(const float* __restrict__ aux,
                       const float* __restrict__ Wlm, const float* __restrict__ blm,
                       const float* __restrict__ gamma, const float* __restrict__ beta,
                       const float* __restrict__ mean, const float* __restrict__ var,
                       const float* __restrict__ W3, const float* __restrict__ b3,
                       const float* __restrict__ W4, const float* __restrict__ b4,
                       float* __restrict__ out) {
    int b = blockIdx.x;
    int t = threadIdx.x;  // 128 threads
    __shared__ float h2s[64], zbn[66], hid[32];

    if (t < 64) h2s[t] = g_h2[b * 64 + t];
    __syncthreads();
    if (t < 66) {
        float z = (t < 2) ? aux[b * 2 + t] : h2s[t - 2];
        zbn[t] = gamma[t] * (z - mean[t]) * rsqrtf(var[t] + 1e-3f) + beta[t];
    }
    __syncthreads();
    if (t < 32) {
        float acc = b3[t];
#pragma unroll
        for (int k = 0; k < 66; k++) acc += zbn[k] * __ldg(&W3[k * 32 + t]);
        hid[t] = fmaxf(acc, 0.0f);
    }
    __syncthreads();
    if (t == 0) {
        float o0 = b4[0], o1 = b4[1];
#pragma unroll
        for (int k = 0; k < 32; k++) {
            o0 += hid[k] * __ldg(&W4[k * 2 + 0]);
            o1 += hid[k] * __ldg(&W4[k * 2 + 1]);
        }
        float m = fmaxf(o0, o1);
        float e0 = __expf(o0 - m), e1 = __expf(o1 - m);
        float inv = 1.0f / (e0 + e1);
        out[b * 2 + 0] = e0 * inv;
        out[b * 2 + 1] = e1 * inv;

        float l0 = blm[0], l1 = blm[1];
#pragma unroll
        for (int k = 0; k < 64; k++) {
            l0 += h2s[k] * __ldg(&Wlm[k * 2 + 0]);
            l1 += h2s[k] * __ldg(&Wlm[k * 2 + 1]);
        }
        out[B_ * 2 + b * 2 + 0] = sigm_(l0);
        out[B_ * 2 + b * 2 + 1] = sigm_(l1);
    }
}

// ---------------------------------------------------------------------------
// launcher
// inputs: 0 aux_in, 1 code_in, 2 emb, 3 W1, 4 U1, 5 b1, 6 W2, 7 U2, 8 b2,
//         9 Wlm, 10 blm, 11 bn_gamma, 12 bn_beta, 13 bn_mean, 14 bn_var,
//         15 W3, 16 b3, 17 W4, 18 b4
// ---------------------------------------------------------------------------
extern "C" void kernel_launch(void* const* d_in, const int* in_sizes, int n_in,
                              void* d_out, int out_size) {
    const float* aux   = (const float*)d_in[0];
    const int*   code  = (const int*)d_in[1];
    const float* emb   = (const float*)d_in[2];
    const float* W1    = (const float*)d_in[3];
    const float* U1    = (const float*)d_in[4];
    const float* b1    = (const float*)d_in[5];
    const float* W2    = (const float*)d_in[6];
    const float* U2    = (const float*)d_in[7];
    const float* b2    = (const float*)d_in[8];
    const float* Wlm   = (const float*)d_in[9];
    const float* blm   = (const float*)d_in[10];
    const float* gamma = (const float*)d_in[11];
    const float* beta  = (const float*)d_in[12];
    const float* mean  = (const float*)d_in[13];
    const float* var   = (const float*)d_in[14];
    const float* W3    = (const float*)d_in[15];
    const float* b3    = (const float*)d_in[16];
    const float* W4    = (const float*)d_in[17];
    const float* b4    = (const float*)d_in[18];
    float* out = (float*)d_out;

    cudaFuncSetAttribute(k_lstm, cudaFuncAttributeMaxDynamicSharedMemorySize,
                         SMEM_BYTES);

    k_embproj<<<V_, 256>>>(emb, W1, b1);
    k_lstm<<<NBLK_, THR_, SMEM_BYTES>>>(code, U1, W2, U2, b2);
    k_head<<<B_, 128>>>(aux, Wlm, blm, gamma, beta, mean, var, W3, b3, W4, b4,
                        out);
}

// round 5
// speedup vs baseline: 1.0383x; 1.0377x over previous
#include <cuda_runtime.h>
#include <cuda_bf16.h>
#include <cstdint>

// ---------------------------------------------------------------------------
// RnnTfModel: emb lookup -> LSTM1 (seq) -> LSTM2 (last) -> heads
// B=512, T=1024, D=H=64, 4H=256, V=8193
//
// R5: split-k 512-thread persistent LSTM. Thread (j, kh): column j, k-half kh.
//     All weights register-resident (96 regs/thread). 4 warps/SMSP hide
//     barrier/activation tails. Partials combined in smem at gate update.
// ---------------------------------------------------------------------------

#define B_   512
#define T_   1024
#define D_   64
#define G4_  256
#define V_   8193
#define NB_  4
#define NBLK_ 128
#define THR_ 512

using ull = unsigned long long;

__device__ float g_table[V_ * G4_];   // projected embedding table (8.4 MB)
__device__ float g_h2[B_ * D_];       // final layer-2 hidden state

__device__ __forceinline__ void ffma2(ull& d, ull a, ull b) {
    asm("fma.rn.f32x2 %0, %1, %2, %0;" : "+l"(d) : "l"(a), "l"(b));
}
__device__ __forceinline__ float2 unpack2(ull v) {
    float2 f;
    asm("mov.b64 {%0, %1}, %2;" : "=f"(f.x), "=f"(f.y) : "l"(v));
    return f;
}
__device__ __forceinline__ ull pack2(float lo, float hi) {
    ull v;
    asm("mov.b64 %0, {%1, %2};" : "=l"(v) : "f"(lo), "f"(hi));
    return v;
}
__device__ __forceinline__ float sigm_(float x) {
    return 1.0f / (1.0f + __expf(-x));
}
__device__ __forceinline__ float tanh_(float x) {
    float e = __expf(-2.0f * x);
    return (1.0f - e) / (1.0f + e);
}

// ---------------------------------------------------------------------------
// Kernel 1: projected embedding table  (g_table = emb @ W1 + b1)
// ---------------------------------------------------------------------------
__global__ void k_embproj(const float* __restrict__ emb,
                          const float* __restrict__ W1,
                          const float* __restrict__ b1) {
    int v = blockIdx.x;
    int j = threadIdx.x;  // 256 threads, one output each
    __shared__ float e[D_];
    if (j < D_) e[j] = emb[v * D_ + j];
    __syncthreads();
    float acc = b1[j];
#pragma unroll
    for (int k = 0; k < D_; k++) acc += e[k] * __ldg(&W1[k * G4_ + j]);
    g_table[v * G4_ + j] = acc;
}

// ---------------------------------------------------------------------------
// Kernel 2: fused persistent 2-layer LSTM, split-k over 512 threads.
//   tid = kh*256 + j :  j = gate column [0,256),  kh = k-half {0,1}.
//   Weights (thread's k-half of column j): U1 16 pairs, W2 16, U2 16 = 96 regs.
//   Partial sums -> zp1/zp2[kh][row][col]; combined by threads 0-255 in the
//   gate-update phases (which also hold c1,c2 state for (r_,u_)).
// ---------------------------------------------------------------------------
__global__ void __launch_bounds__(THR_, 1)
k_lstm(const int* __restrict__ code_in,
       const float* __restrict__ U1,
       const float* __restrict__ W2,
       const float* __restrict__ U2,
       const float* __restrict__ b2) {
    __shared__ __align__(16) float hc[NB_ * 128];   // [0,64)=h1, [64,128)=h2
    __shared__ float zp1[2][NB_][G4_];
    __shared__ float zp2[2][NB_][G4_];
    __shared__ int code_s[NB_ * T_];

    const int tid = threadIdx.x;
    const int j   = tid & 255;   // column
    const int kh  = tid >> 8;    // k-half
    const int r_  = (tid >> 6) & 3;  // update row (threads 0-255)
    const int u_  = tid & 63;        // update unit
    const int b0  = blockIdx.x * NB_;

    // ---- weights into registers: this thread's k-half of column j ----
    ull w1r[16], w2r[16], u2r[16];
#pragma unroll
    for (int k2 = 0; k2 < 16; k2++) {
        int k = kh * 32 + 2 * k2;
        w1r[k2] = pack2(__ldg(&U1[k * G4_ + j]), __ldg(&U1[(k + 1) * G4_ + j]));
        w2r[k2] = pack2(__ldg(&W2[k * G4_ + j]), __ldg(&W2[(k + 1) * G4_ + j]));
        u2r[k2] = pack2(__ldg(&U2[k * G4_ + j]), __ldg(&U2[(k + 1) * G4_ + j]));
    }
    const float b2j = b2[j];

    // ---- codes for this block's 4 rows ----
    for (int i = tid; i < NB_ * T_; i += THR_) {
        int r = i >> 10, t = i & (T_ - 1);
        code_s[i] = code_in[(b0 + r) * T_ + t];
    }
    // ---- zero h state ----
    if (tid < NB_ * 128) hc[tid] = 0.0f;
    __syncthreads();

    float c1 = 0.0f, c2 = 0.0f;

    // prefetch xz for t=0 (only kh==0 warps add xz)
    float cur[NB_] = {0, 0, 0, 0};
    if (kh == 0) {
#pragma unroll
        for (int r = 0; r < NB_; r++)
            cur[r] = __ldg(&g_table[(size_t)code_s[r * T_] * G4_ + j]);
    }

    for (int t = 0; t < T_; t++) {
        float nxt[NB_] = {0, 0, 0, 0};
        if (kh == 0) {
            int tn = (t + 1 < T_) ? (t + 1) : (T_ - 1);
#pragma unroll
            for (int r = 0; r < NB_; r++)
                nxt[r] = __ldg(&g_table[(size_t)code_s[r * T_ + tn] * G4_ + j]);
        }

        // ===== phase A: partial z1 = U1_half . h1_{t-1}  (+xz on kh=0) =====
        {
            ull a0 = 0, a1 = 0, a2 = 0, a3 = 0;
#pragma unroll
            for (int k4 = 0; k4 < 8; k4++) {
                int kk = kh * 8 + k4;
                ulonglong2 h0 = *(const ulonglong2*)&hc[0 * 128 + 4 * kk];
                ulonglong2 h1 = *(const ulonglong2*)&hc[1 * 128 + 4 * kk];
                ulonglong2 h2 = *(const ulonglong2*)&hc[2 * 128 + 4 * kk];
                ulonglong2 h3 = *(const ulonglong2*)&hc[3 * 128 + 4 * kk];
                ffma2(a0, h0.x, w1r[2 * k4]);     ffma2(a0, h0.y, w1r[2 * k4 + 1]);
                ffma2(a1, h1.x, w1r[2 * k4]);     ffma2(a1, h1.y, w1r[2 * k4 + 1]);
                ffma2(a2, h2.x, w1r[2 * k4]);     ffma2(a2, h2.y, w1r[2 * k4 + 1]);
                ffma2(a3, h3.x, w1r[2 * k4]);     ffma2(a3, h3.y, w1r[2 * k4 + 1]);
            }
            float2 p0 = unpack2(a0), p1 = unpack2(a1);
            float2 p2 = unpack2(a2), p3 = unpack2(a3);
            zp1[kh][0][j] = p0.x + p0.y + cur[0];
            zp1[kh][1][j] = p1.x + p1.y + cur[1];
            zp1[kh][2][j] = p2.x + p2.y + cur[2];
            zp1[kh][3][j] = p3.x + p3.y + cur[3];
        }
        __syncthreads();   // S1: zp1 ready

        // ===== update 1 (threads 0-255): combine, activate, h1_t =====
        if (tid < 256) {
            float zi = zp1[0][r_][u_]        + zp1[1][r_][u_];
            float zf = zp1[0][r_][64 + u_]   + zp1[1][r_][64 + u_];
            float zg = zp1[0][r_][128 + u_]  + zp1[1][r_][128 + u_];
            float zo = zp1[0][r_][192 + u_]  + zp1[1][r_][192 + u_];
            float iv = sigm_(zi), fv = sigm_(zf);
            float gv = tanh_(zg), ov = sigm_(zo);
            c1 = fv * c1 + iv * gv;
            hc[r_ * 128 + u_] = ov * tanh_(c1);   // h1_t
        }
        __syncthreads();   // S2: h1_t ready

        // ===== phase B: partial z2 = W2_half.h1_t + U2_half.h2_{t-1} =====
        {
            ull a0 = 0, a1 = 0, a2 = 0, a3 = 0;
#pragma unroll
            for (int k4 = 0; k4 < 8; k4++) {
                int kk = kh * 8 + k4;
                ulonglong2 h0 = *(const ulonglong2*)&hc[0 * 128 + 4 * kk];
                ulonglong2 h1 = *(const ulonglong2*)&hc[1 * 128 + 4 * kk];
                ulonglong2 h2 = *(const ulonglong2*)&hc[2 * 128 + 4 * kk];
                ulonglong2 h3 = *(const ulonglong2*)&hc[3 * 128 + 4 * kk];
                ffma2(a0, h0.x, w2r[2 * k4]);     ffma2(a0, h0.y, w2r[2 * k4 + 1]);
                ffma2(a1, h1.x, w2r[2 * k4]);     ffma2(a1, h1.y, w2r[2 * k4 + 1]);
                ffma2(a2, h2.x, w2r[2 * k4]);     ffma2(a2, h2.y, w2r[2 * k4 + 1]);
                ffma2(a3, h3.x, w2r[2 * k4]);     ffma2(a3, h3.y, w2r[2 * k4 + 1]);
            }
#pragma unroll
            for (int k4 = 0; k4 < 8; k4++) {
                int kk = kh * 8 + k4;
                ulonglong2 h0 = *(const ulonglong2*)&hc[0 * 128 + 64 + 4 * kk];
                ulonglong2 h1 = *(const ulonglong2*)&hc[1 * 128 + 64 + 4 * kk];
                ulonglong2 h2 = *(const ulonglong2*)&hc[2 * 128 + 64 + 4 * kk];
                ulonglong2 h3 = *(const ulonglong2*)&hc[3 * 128 + 64 + 4 * kk];
                ffma2(a0, h0.x, u2r[2 * k4]);     ffma2(a0, h0.y, u2r[2 * k4 + 1]);
                ffma2(a1, h1.x, u2r[2 * k4]);     ffma2(a1, h1.y, u2r[2 * k4 + 1]);
                ffma2(a2, h2.x, u2r[2 * k4]);     ffma2(a2, h2.y, u2r[2 * k4 + 1]);
                ffma2(a3, h3.x, u2r[2 * k4]);     ffma2(a3, h3.y, u2r[2 * k4 + 1]);
            }
            float bb = (kh == 0) ? b2j : 0.0f;
            float2 p0 = unpack2(a0), p1 = unpack2(a1);
            float2 p2 = unpack2(a2), p3 = unpack2(a3);
            zp2[kh][0][j] = p0.x + p0.y + bb;
            zp2[kh][1][j] = p1.x + p1.y + bb;
            zp2[kh][2][j] = p2.x + p2.y + bb;
            zp2[kh][3][j] = p3.x + p3.y + bb;
        }
        __syncthreads();   // S3: zp2 ready

        // ===== update 2 (threads 0-255): combine, activate, h2_t =====
        if (tid < 256) {
            float zi = zp2[0][r_][u_]        + zp2[1][r_][u_];
            float zf = zp2[0][r_][64 + u_]   + zp2[1][r_][64 + u_];
            float zg = zp2[0][r_][128 + u_]  + zp2[1][r_][128 + u_];
            float zo = zp2[0][r_][192 + u_]  + zp2[1][r_][192 + u_];
            float iv = sigm_(zi), fv = sigm_(zf);
            float gv = tanh_(zg), ov = sigm_(zo);
            c2 = fv * c2 + iv * gv;
            hc[r_ * 128 + 64 + u_] = ov * tanh_(c2);  // h2_t
        }
        // no barrier needed:
        //  - h1_t / h2_t next reads are after S1+S2 / S2 of step t+1;
        //  - zp1 WAR (write in phase A of t+1) is after S3 of t;
        //  - zp2 WAR (write in phase B of t+1) is after S1,S2 of t+1.

        if (kh == 0) {
#pragma unroll
            for (int r = 0; r < NB_; r++) cur[r] = nxt[r];
        }
    }

    __syncthreads();
    if (tid < 256) g_h2[(b0 + r_) * D_ + u_] = hc[r_ * 128 + 64 + u_];
}

// ---------------------------------------------------------------------------
// Kernel 3: heads.  out[0:1024] = softmax head, out[1024:2048] = langmodel.
// ---------------------------------------------------------------------------
__global__ void k_head(const float* __restrict__ aux,
                       const float* __restrict__ Wlm, const float* __restrict__ blm,
                       const float* __restrict__ gamma, const float* __restrict__ beta,
                       const float* __restrict__ mean, const float* __restrict__ var,
                       const float* __restrict__ W3, const float* __restrict__ b3,
                       const float* __restrict__ W4, const float* __restrict__ b4,
                       float* __restrict__ out) {
    int b = blockIdx.x;
    int t = threadIdx.x;  // 128 threads
    __shared__ float h2s[64], zbn[66], hid[32];

    if (t < 64) h2s[t] = g_h2[b * 64 + t];
    __syncthreads();
    if (t < 66) {
        float z = (t < 2) ? aux[b * 2 + t] : h2s[t - 2];
        zbn[t] = gamma[t] * (z - mean[t]) * rsqrtf(var[t] + 1e-3f) + beta[t];
    }
    __syncthreads();
    if (t < 32) {
        float acc = b3[t];
#pragma unroll
        for (int k = 0; k < 66; k++) acc += zbn[k] * __ldg(&W3[k * 32 + t]);
        hid[t] = fmaxf(acc, 0.0f);
    }
    __syncthreads();
    if (t == 0) {
        float o0 = b4[0], o1 = b4[1];
#pragma unroll
        for (int k = 0; k < 32; k++) {
            o0 += hid[k] * __ldg(&W4[k * 2 + 0]);
            o1 += hid[k] * __ldg(&W4[k * 2 + 1]);
        }
        float m = fmaxf(o0, o1);
        float e0 = __expf(o0 - m), e1 = __expf(o1 - m);
        float inv = 1.0f / (e0 + e1);
        out[b * 2 + 0] = e0 * inv;
        out[b * 2 + 1] = e1 * inv;

        float l0 = blm[0], l1 = blm[1];
#pragma unroll
        for (int k = 0; k < 64; k++) {
            l0 += h2s[k] * __ldg(&Wlm[k * 2 + 0]);
            l1 += h2s[k] * __ldg(&Wlm[k * 2 + 1]);
        }
        out[B_ * 2 + b * 2 + 0] = sigm_(l0);
        out[B_ * 2 + b * 2 + 1] = sigm_(l1);
    }
}

// ---------------------------------------------------------------------------
// launcher
// inputs: 0 aux_in, 1 code_in, 2 emb, 3 W1, 4 U1, 5 b1, 6 W2, 7 U2, 8 b2,
//         9 Wlm, 10 blm, 11 bn_gamma, 12 bn_beta, 13 bn_mean, 14 bn_var,
//         15 W3, 16 b3, 17 W4, 18 b4
// ---------------------------------------------------------------------------
extern "C" void kernel_launch(void* const* d_in, const int* in_sizes, int n_in,
                              void* d_out, int out_size) {
    const float* aux   = (const float*)d_in[0];
    const int*   code  = (const int*)d_in[1];
    const float* emb   = (const float*)d_in[2];
    const float* W1    = (const float*)d_in[3];
    const float* U1    = (const float*)d_in[4];
    const float* b1    = (const float*)d_in[5];
    const float* W2    = (const float*)d_in[6];
    const float* U2    = (const float*)d_in[7];
    const float* b2    = (const float*)d_in[8];
    const float* Wlm   = (const float*)d_in[9];
    const float* blm   = (const float*)d_in[10];
    const float* gamma = (const float*)d_in[11];
    const float* beta  = (const float*)d_in[12];
    const float* mean  = (const float*)d_in[13];
    const float* var   = (const float*)d_in[14];
    const float* W3    = (const float*)d_in[15];
    const float* b3    = (const float*)d_in[16];
    const float* W4    = (const float*)d_in[17];
    const float* b4    = (const float*)d_in[18];
    float* out = (float*)d_out;

    k_embproj<<<V_, 256>>>(emb, W1, b1);
    k_lstm<<<NBLK_, THR_>>>(code, U1, W2, U2, b2);
    k_head<<<B_, 128>>>(aux, Wlm, blm, gamma, beta, mean, var, W3, b3, W4, b4,
                        out);
}

// round 6
// speedup vs baseline: 1.1028x; 1.0622x over previous
#include <cuda_runtime.h>
#include <cuda_bf16.h>
#include <cstdint>

// ---------------------------------------------------------------------------
// RnnTfModel fully fused: embproj -> grid barrier -> 2-layer LSTM -> head,
// ONE kernel per kernel_launch (so ncu -s 5 -c 1 must capture it).
// B=512, T=1024, D=H=64, 4H=256, V=8193. 128 blocks x 256 threads, 1/SM.
// ---------------------------------------------------------------------------

#define B_   512
#define T_   1024
#define D_   64
#define G4_  256
#define V_   8193
#define NB_  4
#define NBLK_ 128
#define THR_ 256

using ull = unsigned long long;

__device__ float g_table[V_ * G4_];      // projected embedding table (8.4 MB)
__device__ unsigned int g_bar = 0;       // grid-barrier ticket counter

__device__ __forceinline__ void ffma2(ull& d, ull a, ull b) {
    asm("fma.rn.f32x2 %0, %1, %2, %0;" : "+l"(d) : "l"(a), "l"(b));
}
__device__ __forceinline__ float2 unpack2(ull v) {
    float2 f;
    asm("mov.b64 {%0, %1}, %2;" : "=f"(f.x), "=f"(f.y) : "l"(v));
    return f;
}
__device__ __forceinline__ ull pack2(float lo, float hi) {
    ull v;
    asm("mov.b64 %0, {%1, %2};" : "=l"(v) : "f"(lo), "f"(hi));
    return v;
}
__device__ __forceinline__ float sigm_(float x) {
    return 1.0f / (1.0f + __expf(-x));
}
__device__ __forceinline__ float tanh_(float x) {
    float e = __expf(-2.0f * x);
    return (1.0f - e) / (1.0f + e);
}

// ---------------------------------------------------------------------------
// The single fused kernel.
// smem: hc[4*128] ([0,64)=h1,[64,128)=h2), zbuf1/zbuf2[4*256],
//       code_s[4*1024] (reused as 16KB embproj scratch first), head scratch.
// ---------------------------------------------------------------------------
__global__ void __launch_bounds__(THR_, 1)
k_fused(const int* __restrict__ code_in,
        const float* __restrict__ emb,
        const float* __restrict__ W1,
        const float* __restrict__ U1,
        const float* __restrict__ b1,
        const float* __restrict__ W2,
        const float* __restrict__ U2,
        const float* __restrict__ b2,
        const float* __restrict__ aux,
        const float* __restrict__ Wlm, const float* __restrict__ blm,
        const float* __restrict__ gamma, const float* __restrict__ beta,
        const float* __restrict__ mean, const float* __restrict__ var,
        const float* __restrict__ W3, const float* __restrict__ b3,
        const float* __restrict__ W4, const float* __restrict__ b4,
        float* __restrict__ out) {
    __shared__ __align__(16) float hc[NB_ * 128];
    __shared__ float zbuf1[NB_ * G4_];
    __shared__ float zbuf2[NB_ * G4_];
    __shared__ __align__(16) int code_s[NB_ * T_];   // 16 KB, scratch first
    __shared__ float zbn[NB_][66];
    __shared__ float hid[NB_][32];

    const int j  = threadIdx.x;
    const int r_ = j >> 6;
    const int u_ = j & 63;
    const int b0 = blockIdx.x * NB_;

    // =================== phase 0: embproj (this block's 64 vocab rows) =====
    {
        float* esc = (float*)code_s;            // 4096 floats = 64 rows x 64
        const int vbase = blockIdx.x * 64;
        const float b1j = b1[j];

        ull w1c[32];                            // W1 column j, packed k-pairs
#pragma unroll
        for (int k2 = 0; k2 < 32; k2++)
            w1c[k2] = pack2(__ldg(&W1[(2 * k2) * G4_ + j]),
                            __ldg(&W1[(2 * k2 + 1) * G4_ + j]));

        for (int i = j; i < 64 * D_; i += THR_) esc[i] = emb[vbase * D_ + i];
        __syncthreads();

#pragma unroll 4
        for (int r = 0; r < 64; r++) {
            ull acc = 0;
#pragma unroll
            for (int k2 = 0; k2 < 32; k2++)
                ffma2(acc, *(const ull*)&esc[r * D_ + 2 * k2], w1c[k2]);
            float2 p = unpack2(acc);
            g_table[(size_t)(vbase + r) * G4_ + j] = b1j + p.x + p.y;
        }
        if (blockIdx.x == 0) {                  // leftover vocab row 8192
            ull acc = 0;
#pragma unroll
            for (int k2 = 0; k2 < 32; k2++)
                ffma2(acc, pack2(__ldg(&emb[8192 * D_ + 2 * k2]),
                                 __ldg(&emb[8192 * D_ + 2 * k2 + 1])), w1c[k2]);
            float2 p = unpack2(acc);
            g_table[(size_t)8192 * G4_ + j] = b1j + p.x + p.y;
        }
        __syncthreads();                        // esc dead, code_s reusable
    }

    // ============ load LSTM weights into RF + codes + init state ===========
    ull w1r[32], w2r[64];
#pragma unroll
    for (int k2 = 0; k2 < 32; k2++)
        w1r[k2] = pack2(__ldg(&U1[(2 * k2) * G4_ + j]),
                        __ldg(&U1[(2 * k2 + 1) * G4_ + j]));
#pragma unroll
    for (int k2 = 0; k2 < 32; k2++) {
        w2r[k2]      = pack2(__ldg(&W2[(2 * k2) * G4_ + j]),
                             __ldg(&W2[(2 * k2 + 1) * G4_ + j]));
        w2r[32 + k2] = pack2(__ldg(&U2[(2 * k2) * G4_ + j]),
                             __ldg(&U2[(2 * k2 + 1) * G4_ + j]));
    }
    for (int i = j; i < NB_ * T_; i += THR_) {
        int r = i >> 10, t = i & (T_ - 1);
        code_s[i] = code_in[(b0 + r) * T_ + t];
    }
    hc[j] = 0.0f;
    hc[j + 256] = 0.0f;
    const float b2j = b2[j];

    // =================== grid barrier (all 128 blocks resident) ===========
    __threadfence();                // my g_table stores -> device scope
    __syncthreads();                // all threads of block arrived & fenced
    if (j == 0) {
        unsigned int ticket = atomicAdd(&g_bar, 1u);
        unsigned int target = (ticket / NBLK_ + 1u) * NBLK_;
        volatile unsigned int* p = &g_bar;
        while (*p < target) __nanosleep(64);
    }
    __syncthreads();                // whole block released; L1 cold -> safe

    float c1 = 0.0f, c2 = 0.0f;

    float cur[NB_];
#pragma unroll
    for (int r = 0; r < NB_; r++)
        cur[r] = __ldg(&g_table[(size_t)code_s[r * T_] * G4_ + j]);

    const bool isg = ((j >> 6) == 2);  // gate 2 = g (tanh)

    // ============================ LSTM loop ================================
    for (int t = 0; t < T_; t++) {
        float nxt[NB_];
        int tn = (t + 1 < T_) ? (t + 1) : (T_ - 1);
#pragma unroll
        for (int r = 0; r < NB_; r++)
            nxt[r] = __ldg(&g_table[(size_t)code_s[r * T_ + tn] * G4_ + j]);

        // ---- layer 1 matvec: z1 = xz + U1 . h1_{t-1} ----
        ull a0 = 0, a1 = 0, a2 = 0, a3 = 0;
#pragma unroll
        for (int k4 = 0; k4 < 16; k4++) {
            ulonglong2 h0 = *(const ulonglong2*)&hc[0 * 128 + 4 * k4];
            ulonglong2 h1 = *(const ulonglong2*)&hc[1 * 128 + 4 * k4];
            ulonglong2 h2 = *(const ulonglong2*)&hc[2 * 128 + 4 * k4];
            ulonglong2 h3 = *(const ulonglong2*)&hc[3 * 128 + 4 * k4];
            ffma2(a0, h0.x, w1r[2 * k4]);     ffma2(a1, h1.x, w1r[2 * k4]);
            ffma2(a2, h2.x, w1r[2 * k4]);     ffma2(a3, h3.x, w1r[2 * k4]);
            ffma2(a0, h0.y, w1r[2 * k4 + 1]); ffma2(a1, h1.y, w1r[2 * k4 + 1]);
            ffma2(a2, h2.y, w1r[2 * k4 + 1]); ffma2(a3, h3.y, w1r[2 * k4 + 1]);
        }
        {
            ull aa[NB_] = {a0, a1, a2, a3};
#pragma unroll
            for (int r = 0; r < NB_; r++) {
                float2 p = unpack2(aa[r]);
                float z = cur[r] + p.x + p.y;
                zbuf1[r * G4_ + j] = isg ? tanh_(z) : sigm_(z);
            }
        }
        __syncthreads();   // S1
        {
            float iv = zbuf1[r_ * G4_ + u_];
            float fv = zbuf1[r_ * G4_ + 64 + u_];
            float gv = zbuf1[r_ * G4_ + 128 + u_];
            float ov = zbuf1[r_ * G4_ + 192 + u_];
            c1 = fv * c1 + iv * gv;
            hc[r_ * 128 + u_] = ov * tanh_(c1);   // h1_t
        }
        __syncthreads();   // S2

        // ---- layer 2 matvec: z2 = b2 + [h1_t, h2_{t-1}] . [W2;U2] ----
        a0 = a1 = a2 = a3 = 0;
#pragma unroll
        for (int k4 = 0; k4 < 32; k4++) {
            ulonglong2 h0 = *(const ulonglong2*)&hc[0 * 128 + 4 * k4];
            ulonglong2 h1 = *(const ulonglong2*)&hc[1 * 128 + 4 * k4];
            ulonglong2 h2 = *(const ulonglong2*)&hc[2 * 128 + 4 * k4];
            ulonglong2 h3 = *(const ulonglong2*)&hc[3 * 128 + 4 * k4];
            ffma2(a0, h0.x, w2r[2 * k4]);     ffma2(a1, h1.x, w2r[2 * k4]);
            ffma2(a2, h2.x, w2r[2 * k4]);     ffma2(a3, h3.x, w2r[2 * k4]);
            ffma2(a0, h0.y, w2r[2 * k4 + 1]); ffma2(a1, h1.y, w2r[2 * k4 + 1]);
            ffma2(a2, h2.y, w2r[2 * k4 + 1]); ffma2(a3, h3.y, w2r[2 * k4 + 1]);
        }
        {
            ull aa[NB_] = {a0, a1, a2, a3};
#pragma unroll
            for (int r = 0; r < NB_; r++) {
                float2 p = unpack2(aa[r]);
                float z = b2j + p.x + p.y;
                zbuf2[r * G4_ + j] = isg ? tanh_(z) : sigm_(z);
            }
        }
        __syncthreads();   // S3
        {
            float iv = zbuf2[r_ * G4_ + u_];
            float fv = zbuf2[r_ * G4_ + 64 + u_];
            float gv = zbuf2[r_ * G4_ + 128 + u_];
            float ov = zbuf2[r_ * G4_ + 192 + u_];
            c2 = fv * c2 + iv * gv;
            hc[r_ * 128 + 64 + u_] = ov * tanh_(c2);  // h2_t
        }
        // no barrier: h2_t next read after S1+S2 of t+1; zbuf WARs covered.

#pragma unroll
        for (int r = 0; r < NB_; r++) cur[r] = nxt[r];
    }

    __syncthreads();

    // ============================ head (4 rows) ============================
    if (j < 264) {                       // 4 rows x 66 features
        int r = j / 66, k = j % 66;
        float v = (k < 2) ? aux[(b0 + r) * 2 + k] : hc[r * 128 + 64 + (k - 2)];
        zbn[r][k] = gamma[k] * (v - mean[k]) * rsqrtf(var[k] + 1e-3f) + beta[k];
    }
    __syncthreads();
    if (j < 128) {                       // 4 rows x 32 hidden
        int r = j >> 5, i = j & 31;
        float acc = b3[i];
#pragma unroll
        for (int k = 0; k < 66; k++) acc += zbn[r][k] * __ldg(&W3[k * 32 + i]);
        hid[r][i] = fmaxf(acc, 0.0f);
    }
    __syncthreads();
    if (j < NB_) {
        int r = j;
        float o0 = b4[0], o1 = b4[1];
#pragma unroll
        for (int k = 0; k < 32; k++) {
            o0 += hid[r][k] * __ldg(&W4[k * 2 + 0]);
            o1 += hid[r][k] * __ldg(&W4[k * 2 + 1]);
        }
        float m = fmaxf(o0, o1);
        float e0 = __expf(o0 - m), e1 = __expf(o1 - m);
        float inv = 1.0f / (e0 + e1);
        out[(b0 + r) * 2 + 0] = e0 * inv;
        out[(b0 + r) * 2 + 1] = e1 * inv;

        float l0 = blm[0], l1 = blm[1];
#pragma unroll
        for (int k = 0; k < 64; k++) {
            float h = hc[r * 128 + 64 + k];
            l0 += h * __ldg(&Wlm[k * 2 + 0]);
            l1 += h * __ldg(&Wlm[k * 2 + 1]);
        }
        out[B_ * 2 + (b0 + r) * 2 + 0] = sigm_(l0);
        out[B_ * 2 + (b0 + r) * 2 + 1] = sigm_(l1);
    }
}

// ---------------------------------------------------------------------------
// launcher — ONE kernel, so every ncu launch slot captures it.
// inputs: 0 aux_in, 1 code_in, 2 emb, 3 W1, 4 U1, 5 b1, 6 W2, 7 U2, 8 b2,
//         9 Wlm, 10 blm, 11 bn_gamma, 12 bn_beta, 13 bn_mean, 14 bn_var,
//         15 W3, 16 b3, 17 W4, 18 b4
// ---------------------------------------------------------------------------
extern "C" void kernel_launch(void* const* d_in, const int* in_sizes, int n_in,
                              void* d_out, int out_size) {
    const float* aux   = (const float*)d_in[0];
    const int*   code  = (const int*)d_in[1];
    const float* emb   = (const float*)d_in[2];
    const float* W1    = (const float*)d_in[3];
    const float* U1    = (const float*)d_in[4];
    const float* b1    = (const float*)d_in[5];
    const float* W2    = (const float*)d_in[6];
    const float* U2    = (const float*)d_in[7];
    const float* b2    = (const float*)d_in[8];
    const float* Wlm   = (const float*)d_in[9];
    const float* blm   = (const float*)d_in[10];
    const float* gamma = (const float*)d_in[11];
    const float* beta  = (const float*)d_in[12];
    const float* mean  = (const float*)d_in[13];
    const float* var   = (const float*)d_in[14];
    const float* W3    = (const float*)d_in[15];
    const float* b3    = (const float*)d_in[16];
    const float* W4    = (const float*)d_in[17];
    const float* b4    = (const float*)d_in[18];
    float* out = (float*)d_out;

    k_fused<<<NBLK_, THR_>>>(code, emb, W1, U1, b1, W2, U2, b2,
                             aux, Wlm, blm, gamma, beta, mean, var,
                             W3, b3, W4, b4, out);
}